// round 5
// baseline (speedup 1.0000x reference)
#include <cuda_runtime.h>
#include <cuda_fp16.h>
#include <math.h>
#include <stdint.h>

#define B_    256
#define D_    2048
#define NM    16384      // C_CAM * P
#define P_    2048
#define CCAM  8
#define KTOP  50
#define TINV  (1.0f/0.07f)

// scratch (static device globals — no allocation allowed)
__device__ __align__(16) uint32_t g_xh[B_ * D_ / 2];   // fp16 normalized inputs, 1 MB
__device__ __align__(16) uint32_t g_vh[NM * D_ / 2];   // fp16 tempV, 64 MB
__device__ float g_logits[B_ * NM];                    // all_logits, 16 MB
__device__ float g_ce[B_];
__device__ float g_lossk[B_];

// ---------------------------------------------------------------------------
__device__ __forceinline__ uint32_t smem_u32(const void* p) {
    uint32_t a;
    asm("{ .reg .u64 t; cvta.to.shared.u64 t, %1; cvt.u32.u64 %0, t; }"
        : "=r"(a) : "l"(p));
    return a;
}
__device__ __forceinline__ void cpa16(uint32_t s, const void* g) {
    asm volatile("cp.async.cg.shared.global [%0], [%1], 16;" :: "r"(s), "l"(g) : "memory");
}
// pack two fp32 -> f16x2 (memory order: v.x low, v.y high)
__device__ __forceinline__ uint32_t packh(float2 v) {
    uint32_t r;
    asm("cvt.rn.f16x2.f32 %0, %1, %2;" : "=r"(r) : "f"(v.y), "f"(v.x));
    return r;
}
#define LDSM4(r0, r1, r2, r3, a) \
    asm volatile("ldmatrix.sync.aligned.m8n8.x4.shared.b16 {%0,%1,%2,%3}, [%4];" \
                 : "=r"(r0), "=r"(r1), "=r"(r2), "=r"(r3) : "r"(a))

// ---------------------------------------------------------------------------
// Kernel 0: tempV fp32 -> fp16 (8 floats per thread)
// ---------------------------------------------------------------------------
__global__ void __launch_bounds__(256) kcvt(const float* __restrict__ V) {
    size_t i = (size_t)blockIdx.x * 256 + threadIdx.x;     // 4.19M threads
    const float4* src = (const float4*)V;
    float4 a = src[2 * i], b = src[2 * i + 1];
    uint4 o;
    o.x = packh(make_float2(a.x, a.y));
    o.y = packh(make_float2(a.z, a.w));
    o.z = packh(make_float2(b.x, b.y));
    o.w = packh(make_float2(b.z, b.w));
    ((uint4*)g_vh)[i] = o;
}

// ---------------------------------------------------------------------------
// Kernel 1: L2-normalize each input row -> fp16
// ---------------------------------------------------------------------------
__global__ void __launch_bounds__(256) knorm(const float* __restrict__ x) {
    __shared__ float red[8];
    int b = blockIdx.x;
    int t = threadIdx.x;
    const float* row = x + (size_t)b * D_;
    float s = 0.f;
    for (int i = t; i < D_; i += 256) { float v = row[i]; s += v * v; }
    #pragma unroll
    for (int o = 16; o > 0; o >>= 1) s += __shfl_down_sync(0xffffffffu, s, o);
    if ((t & 31) == 0) red[t >> 5] = s;
    __syncthreads();
    if (t < 8) {
        float w = red[t];
        #pragma unroll
        for (int o = 4; o > 0; o >>= 1) w += __shfl_down_sync(0xffu, w, o);
        if (t == 0) red[0] = w;
    }
    __syncthreads();
    float inv = rsqrtf(red[0]);
    const float2* r2 = (const float2*)row;
    for (int i = t; i < D_ / 2; i += 256) {
        float2 v = r2[i];
        g_xh[b * (D_ / 2) + i] = packh(make_float2(v.x * inv, v.y * inv));
    }
}

// ---------------------------------------------------------------------------
// Kernel 2: fp16 ldmatrix + mma.sync GEMM  C[256,16384] = xh @ Vh^T
// CTA 128x128, BK=64 halfs, 8 warps (warp tile 64x32), cp.async double buffer.
// SMEM rows: 64 halfs data padded to 144 B (stride%128B==16B -> LDSM conflict-free)
// ---------------------------------------------------------------------------
#define BM 128
#define BN 128
#define BKH 64
#define NCH (D_ / BKH)           // 32
#define ROWB 144                 // bytes per SMEM row (128 data + 16 pad)
#define ATILE_B (BM * ROWB)      // 18432 B
#define STAGE_B (2 * ATILE_B)    // 36864 B
#define GEMM_SMEM (2 * STAGE_B)  // 73728 B

__global__ void __launch_bounds__(256, 2) kgemm() {
    extern __shared__ char sm[];
    uint32_t sbase = smem_u32(sm);
    int t = threadIdx.x, lane = t & 31, wid = t >> 5;
    int warp_m = (wid & 1) * 64, warp_n = (wid >> 1) * 32;
    int gid = lane >> 2, tig = lane & 3;
    int mBase = blockIdx.y * BM, nBase = blockIdx.x * BN;

    float acc[4][4][4];
    #pragma unroll
    for (int i = 0; i < 4; i++)
        #pragma unroll
        for (int j = 0; j < 4; j++)
            #pragma unroll
            for (int q = 0; q < 4; q++) acc[i][j][q] = 0.f;

    const char* xhb = (const char*)g_xh;
    const char* vhb = (const char*)g_vh;

    auto loadc = [&](int stage, int c) {
        int k0 = c * BKH;
        uint32_t As = sbase + stage * STAGE_B;
        uint32_t Bs = As + ATILE_B;
        #pragma unroll
        for (int r = 0; r < 4; r++) {
            int i = t + r * 256, row = i >> 3, q = i & 7;
            cpa16(As + (uint32_t)(row * ROWB + q * 16),
                  xhb + ((size_t)(mBase + row) * D_ + k0 + q * 8) * 2);
        }
        #pragma unroll
        for (int r = 0; r < 4; r++) {
            int i = t + r * 256, row = i >> 3, q = i & 7;
            cpa16(Bs + (uint32_t)(row * ROWB + q * 16),
                  vhb + ((size_t)(nBase + row) * D_ + k0 + q * 8) * 2);
        }
    };

    // ldmatrix lane-relative offsets (bytes), fixed per thread
    uint32_t aoff = (uint32_t)((lane & 15) * ROWB + (lane >> 4) * 16);
    uint32_t boff = (uint32_t)(((lane & 7) + ((lane >> 4) << 3)) * ROWB
                               + (((lane >> 3) & 1) * 16));

    loadc(0, 0); asm volatile("cp.async.commit_group;" ::: "memory");
    loadc(1, 1); asm volatile("cp.async.commit_group;" ::: "memory");

    for (int c = 0; c < NCH; c++) {
        asm volatile("cp.async.wait_group 1;" ::: "memory");
        __syncthreads();
        uint32_t As = sbase + (c & 1) * STAGE_B;
        uint32_t Bs = As + ATILE_B;
        #pragma unroll
        for (int kk = 0; kk < 4; kk++) {          // four k16 steps cover BKH=64
            uint32_t a[4][4], b[4][2];
            #pragma unroll
            for (int mt = 0; mt < 4; mt++) {
                uint32_t ad = As + (uint32_t)((warp_m + mt * 16) * ROWB + kk * 32) + aoff;
                LDSM4(a[mt][0], a[mt][1], a[mt][2], a[mt][3], ad);
            }
            #pragma unroll
            for (int np = 0; np < 2; np++) {
                uint32_t bd = Bs + (uint32_t)((warp_n + np * 16) * ROWB + kk * 32) + boff;
                LDSM4(b[2 * np][0], b[2 * np][1], b[2 * np + 1][0], b[2 * np + 1][1], bd);
            }
            #pragma unroll
            for (int mt = 0; mt < 4; mt++)
                #pragma unroll
                for (int nt = 0; nt < 4; nt++)
                    asm volatile(
                        "mma.sync.aligned.m16n8k16.row.col.f32.f16.f16.f32 "
                        "{%0,%1,%2,%3},{%4,%5,%6,%7},{%8,%9},{%0,%1,%2,%3};"
                        : "+f"(acc[mt][nt][0]), "+f"(acc[mt][nt][1]),
                          "+f"(acc[mt][nt][2]), "+f"(acc[mt][nt][3])
                        : "r"(a[mt][0]), "r"(a[mt][1]), "r"(a[mt][2]), "r"(a[mt][3]),
                          "r"(b[nt][0]), "r"(b[nt][1]));
        }
        __syncthreads();
        if (c + 2 < NCH) loadc(c & 1, c + 2);
        asm volatile("cp.async.commit_group;" ::: "memory");
    }

    // epilogue: direct fp32 stores (float2 per c-pair)
    #pragma unroll
    for (int mt = 0; mt < 4; mt++) {
        int row0 = mBase + warp_m + mt * 16 + gid;
        #pragma unroll
        for (int nt = 0; nt < 4; nt++) {
            int col = nBase + warp_n + nt * 8 + 2 * tig;
            *(float2*)(g_logits + (size_t)row0 * NM + col) =
                make_float2(acc[mt][nt][0], acc[mt][nt][1]);
            *(float2*)(g_logits + (size_t)(row0 + 8) * NM + col) =
                make_float2(acc[mt][nt][2], acc[mt][nt][3]);
        }
    }
}

// ---------------------------------------------------------------------------
// Kernel 3: per-sample reductions, incremental top-K
// ---------------------------------------------------------------------------
__device__ __forceinline__ float blockMaxF(float v, float* scratch) {
    int t = threadIdx.x;
    #pragma unroll
    for (int o = 16; o > 0; o >>= 1) v = fmaxf(v, __shfl_down_sync(0xffffffffu, v, o));
    if ((t & 31) == 0) scratch[t >> 5] = v;
    __syncthreads();
    if (t < 8) {
        float w = scratch[t];
        #pragma unroll
        for (int o = 4; o > 0; o >>= 1) w = fmaxf(w, __shfl_down_sync(0xffu, w, o));
        if (t == 0) scratch[0] = w;
    }
    __syncthreads();
    float r = scratch[0];
    __syncthreads();
    return r;
}
__device__ __forceinline__ float blockSumF(float v, float* scratch) {
    int t = threadIdx.x;
    #pragma unroll
    for (int o = 16; o > 0; o >>= 1) v += __shfl_down_sync(0xffffffffu, v, o);
    if ((t & 31) == 0) scratch[t >> 5] = v;
    __syncthreads();
    if (t < 8) {
        float w = scratch[t];
        #pragma unroll
        for (int o = 4; o > 0; o >>= 1) w += __shfl_down_sync(0xffu, w, o);
        if (t == 0) scratch[0] = w;
    }
    __syncthreads();
    float r = scratch[0];
    __syncthreads();
    return r;
}
__device__ __forceinline__ unsigned long long packVI(float f, int idx) {
    unsigned u = __float_as_uint(f);
    u = (u & 0x80000000u) ? ~u : (u | 0x80000000u);     // order-preserving
    return ((unsigned long long)u << 32) | (unsigned)idx;
}

__global__ void __launch_bounds__(256) krow(const int* __restrict__ labels,
                                            const int* __restrict__ cams) {
    extern __shared__ float sv[];                 // NM floats (64 KB)
    __shared__ unsigned long long arr[256];
    __shared__ float fred[8];
    __shared__ unsigned long long wred[8];
    __shared__ unsigned long long s_win;
    __shared__ float s_ori[CCAM];

    int b = blockIdx.x;
    int t = threadIdx.x;
    const float* row = g_logits + (size_t)b * NM;
    for (int i = t; i < NM; i += 256) sv[i] = row[i];
    __syncthreads();

    int cam = cams[b];
    int lab = labels[b];

    // ---- intra-camera CE (unmasked values) ----
    int base = cam * P_;
    float mx = -INFINITY;
    for (int i = t; i < P_; i += 256) mx = fmaxf(mx, sv[base + i]);
    float mxall = blockMaxF(mx, fred);
    float s = 0.f;
    for (int i = t; i < P_; i += 256) s += expf((sv[base + i] - mxall) * TINV);
    float sall = blockSumF(s, fred);
    if (t == 0) {
        float lse = mxall * TINV + logf(sall);
        g_ce[b] = lse - sv[base + lab] * TINV;
    }
    __syncthreads();

    // ---- inter-camera: capture positives, then mask them ----
    float maxori = -INFINITY;
    if (t == 0) {
        #pragma unroll
        for (int c = 0; c < CCAM; c++) {
            s_ori[c] = sv[lab + P_ * c];
            maxori = fmaxf(maxori, s_ori[c]);
        }
        #pragma unroll
        for (int c = 0; c < CCAM; c++) sv[lab + P_ * c] = -10000.0f;
    }
    __syncthreads();

    // ---- initial per-thread max over strided slice ----
    unsigned long long best = 0ull;
    #pragma unroll 8
    for (int j = 0; j < NM / 256; j++) {
        int i = t + 256 * j;
        unsigned long long p = packVI(sv[i], i);
        if (p > best) best = p;
    }
    arr[t] = best;
    __syncthreads();

    // ---- 50 incremental argmax passes ----
    float m = 0.f, ssum = 0.f;    // thread 0 state
    for (int it = 0; it < KTOP; ++it) {
        unsigned long long v = arr[t];
        #pragma unroll
        for (int o = 16; o > 0; o >>= 1) {
            unsigned long long q = __shfl_down_sync(0xffffffffu, v, o);
            if (q > v) v = q;
        }
        if ((t & 31) == 0) wred[t >> 5] = v;
        __syncthreads();
        if (t < 8) {
            unsigned long long w = wred[t];
            #pragma unroll
            for (int o = 4; o > 0; o >>= 1) {
                unsigned long long q = __shfl_down_sync(0xffu, w, o);
                if (q > w) w = q;
            }
            if (t == 0) s_win = w;
        }
        __syncthreads();
        unsigned long long win = s_win;
        int idx = (int)(win & 0xffffffffu);
        if (t == 0) {
            unsigned u = (unsigned)(win >> 32);
            float val = (u & 0x80000000u) ? __uint_as_float(u ^ 0x80000000u)
                                          : __uint_as_float(~u);
            if (it == 0) {
                m = fmaxf(val, maxori);
                ssum = 0.f;
                #pragma unroll
                for (int c = 0; c < CCAM; c++) ssum += expf((s_ori[c] - m) * TINV);
            }
            ssum += expf((val - m) * TINV);
        }
        if (t == (idx & 255)) {           // owner rescans its 64-elem slice
            sv[idx] = -INFINITY;
            unsigned long long nb = 0ull;
            #pragma unroll 8
            for (int j = 0; j < NM / 256; j++) {
                int i = t + 256 * j;
                unsigned long long p = packVI(sv[i], i);
                if (p > nb) nb = p;
            }
            arr[t] = nb;
        }
        __syncthreads();
    }
    if (t == 0) {
        float lse = m * TINV + logf(ssum);
        float mean = 0.f;
        #pragma unroll
        for (int c = 0; c < CCAM; c++) mean += s_ori[c];
        mean = mean * TINV / (float)CCAM;
        g_lossk[b] = lse - mean;
    }
}

// ---------------------------------------------------------------------------
// Kernel 4: deterministic per-camera segment means -> 2 scalars
// ---------------------------------------------------------------------------
__global__ void __launch_bounds__(256) kfinal(const int* __restrict__ cams,
                                              float* __restrict__ out) {
    __shared__ int sc_cam[B_];
    __shared__ float sce[B_], slk[B_];
    __shared__ float mce[CCAM], mlk[CCAM];
    int t = threadIdx.x;
    sc_cam[t] = cams[t];
    sce[t] = g_ce[t];
    slk[t] = g_lossk[t];
    __syncthreads();
    if (t < CCAM) {
        float sc = 0.f, sl = 0.f; int cnt = 0;
        for (int i = 0; i < B_; i++) {
            if (sc_cam[i] == t) { sc += sce[i]; sl += slk[i]; cnt++; }
        }
        mce[t] = (cnt > 0) ? sc / (float)cnt : 0.f;
        mlk[t] = (cnt > 0) ? sl / (float)cnt : 0.f;
    }
    __syncthreads();
    if (t == 0) {
        float li = 0.f, lk = 0.f;
        #pragma unroll
        for (int c = 0; c < CCAM; c++) { li += mce[c]; lk += mlk[c]; }
        out[0] = li;
        out[1] = 0.5f * lk;   // LOSS_WEIGHT
    }
}

// ---------------------------------------------------------------------------
extern "C" void kernel_launch(void* const* d_in, const int* in_sizes, int n_in,
                              void* d_out, int out_size) {
    const float* x      = (const float*)d_in[0];
    const int*   labels = (const int*)d_in[1];
    const int*   cams   = (const int*)d_in[2];
    const float* tempV  = (const float*)d_in[3];
    float* out = (float*)d_out;

    kcvt<<<(NM * D_ / 8) / 256, 256>>>(tempV);
    knorm<<<B_, 256>>>(x);

    cudaFuncSetAttribute(kgemm, cudaFuncAttributeMaxDynamicSharedMemorySize,
                         GEMM_SMEM);
    dim3 g(NM / BN, B_ / BM);          // 128 x 2 = 256 CTAs
    kgemm<<<g, 256, GEMM_SMEM>>>();

    cudaFuncSetAttribute(krow, cudaFuncAttributeMaxDynamicSharedMemorySize,
                         NM * (int)sizeof(float) + 1024);
    krow<<<B_, 256, NM * sizeof(float)>>>(labels, cams);

    kfinal<<<1, 256>>>(cams, out);
}

// round 6
// speedup vs baseline: 1.4358x; 1.4358x over previous
#include <cuda_runtime.h>
#include <cuda_fp16.h>
#include <math.h>
#include <stdint.h>

#define B_    256
#define D_    2048
#define NM    16384      // C_CAM * P
#define P_    2048
#define CCAM  8
#define KTOP  50
#define TINV  (1.0f/0.07f)

// scratch (static device globals — no allocation allowed)
__device__ __align__(16) uint32_t g_xh[B_ * D_ / 2];   // fp16 normalized inputs, 1 MB
__device__ __align__(16) uint32_t g_vh[NM * D_ / 2];   // fp16 tempV, 64 MB
__device__ float g_logits[B_ * NM];                    // all_logits, 16 MB
__device__ float g_ce[B_];
__device__ float g_lossk[B_];

// ---------------------------------------------------------------------------
__device__ __forceinline__ uint32_t smem_u32(const void* p) {
    uint32_t a;
    asm("{ .reg .u64 t; cvta.to.shared.u64 t, %1; cvt.u32.u64 %0, t; }"
        : "=r"(a) : "l"(p));
    return a;
}
__device__ __forceinline__ void cpa16(uint32_t s, const void* g) {
    asm volatile("cp.async.cg.shared.global [%0], [%1], 16;" :: "r"(s), "l"(g) : "memory");
}
// pack two fp32 -> f16x2 (memory order: v.x low, v.y high)
__device__ __forceinline__ uint32_t packh(float2 v) {
    uint32_t r;
    asm("cvt.rn.f16x2.f32 %0, %1, %2;" : "=r"(r) : "f"(v.y), "f"(v.x));
    return r;
}
__device__ __forceinline__ uint32_t ordu(float f) {
    uint32_t u = __float_as_uint(f);
    return (u & 0x80000000u) ? ~u : (u | 0x80000000u);
}
#define LDSM4(r0, r1, r2, r3, a) \
    asm volatile("ldmatrix.sync.aligned.m8n8.x4.shared.b16 {%0,%1,%2,%3}, [%4];" \
                 : "=r"(r0), "=r"(r1), "=r"(r2), "=r"(r3) : "r"(a))

// ---------------------------------------------------------------------------
// Kernel 0: tempV fp32 -> fp16 (8 floats per thread)
// ---------------------------------------------------------------------------
__global__ void __launch_bounds__(256) kcvt(const float* __restrict__ V) {
    size_t i = (size_t)blockIdx.x * 256 + threadIdx.x;
    const float4* src = (const float4*)V;
    float4 a = src[2 * i], b = src[2 * i + 1];
    uint4 o;
    o.x = packh(make_float2(a.x, a.y));
    o.y = packh(make_float2(a.z, a.w));
    o.z = packh(make_float2(b.x, b.y));
    o.w = packh(make_float2(b.z, b.w));
    ((uint4*)g_vh)[i] = o;
}

// ---------------------------------------------------------------------------
// Kernel 1: L2-normalize each input row -> fp16
// ---------------------------------------------------------------------------
__global__ void __launch_bounds__(256) knorm(const float* __restrict__ x) {
    __shared__ float red[8];
    int b = blockIdx.x;
    int t = threadIdx.x;
    const float* row = x + (size_t)b * D_;
    float s = 0.f;
    for (int i = t; i < D_; i += 256) { float v = row[i]; s += v * v; }
    #pragma unroll
    for (int o = 16; o > 0; o >>= 1) s += __shfl_down_sync(0xffffffffu, s, o);
    if ((t & 31) == 0) red[t >> 5] = s;
    __syncthreads();
    if (t < 8) {
        float w = red[t];
        #pragma unroll
        for (int o = 4; o > 0; o >>= 1) w += __shfl_down_sync(0xffu, w, o);
        if (t == 0) red[0] = w;
    }
    __syncthreads();
    float inv = rsqrtf(red[0]);
    const float2* r2 = (const float2*)row;
    for (int i = t; i < D_ / 2; i += 256) {
        float2 v = r2[i];
        g_xh[b * (D_ / 2) + i] = packh(make_float2(v.x * inv, v.y * inv));
    }
}

// ---------------------------------------------------------------------------
// Kernel 2: fp16 ldmatrix + mma.sync GEMM  C[256,16384] = xh @ Vh^T
// ---------------------------------------------------------------------------
#define BM 128
#define BN 128
#define BKH 64
#define NCH (D_ / BKH)           // 32
#define ROWB 144                 // bytes per SMEM row (128 data + 16 pad)
#define ATILE_B (BM * ROWB)
#define STAGE_B (2 * ATILE_B)
#define GEMM_SMEM (2 * STAGE_B)  // 73728 B

__global__ void __launch_bounds__(256, 2) kgemm() {
    extern __shared__ char sm[];
    uint32_t sbase = smem_u32(sm);
    int t = threadIdx.x, lane = t & 31, wid = t >> 5;
    int warp_m = (wid & 1) * 64, warp_n = (wid >> 1) * 32;
    int gid = lane >> 2, tig = lane & 3;
    int mBase = blockIdx.y * BM, nBase = blockIdx.x * BN;

    float acc[4][4][4];
    #pragma unroll
    for (int i = 0; i < 4; i++)
        #pragma unroll
        for (int j = 0; j < 4; j++)
            #pragma unroll
            for (int q = 0; q < 4; q++) acc[i][j][q] = 0.f;

    const char* xhb = (const char*)g_xh;
    const char* vhb = (const char*)g_vh;

    auto loadc = [&](int stage, int c) {
        int k0 = c * BKH;
        uint32_t As = sbase + stage * STAGE_B;
        uint32_t Bs = As + ATILE_B;
        #pragma unroll
        for (int r = 0; r < 4; r++) {
            int i = t + r * 256, row = i >> 3, q = i & 7;
            cpa16(As + (uint32_t)(row * ROWB + q * 16),
                  xhb + ((size_t)(mBase + row) * D_ + k0 + q * 8) * 2);
        }
        #pragma unroll
        for (int r = 0; r < 4; r++) {
            int i = t + r * 256, row = i >> 3, q = i & 7;
            cpa16(Bs + (uint32_t)(row * ROWB + q * 16),
                  vhb + ((size_t)(nBase + row) * D_ + k0 + q * 8) * 2);
        }
    };

    uint32_t aoff = (uint32_t)((lane & 15) * ROWB + (lane >> 4) * 16);
    uint32_t boff = (uint32_t)(((lane & 7) + ((lane >> 4) << 3)) * ROWB
                               + (((lane >> 3) & 1) * 16));

    loadc(0, 0); asm volatile("cp.async.commit_group;" ::: "memory");
    loadc(1, 1); asm volatile("cp.async.commit_group;" ::: "memory");

    for (int c = 0; c < NCH; c++) {
        asm volatile("cp.async.wait_group 1;" ::: "memory");
        __syncthreads();
        uint32_t As = sbase + (c & 1) * STAGE_B;
        uint32_t Bs = As + ATILE_B;
        #pragma unroll
        for (int kk = 0; kk < 4; kk++) {
            uint32_t a[4][4], b[4][2];
            #pragma unroll
            for (int mt = 0; mt < 4; mt++) {
                uint32_t ad = As + (uint32_t)((warp_m + mt * 16) * ROWB + kk * 32) + aoff;
                LDSM4(a[mt][0], a[mt][1], a[mt][2], a[mt][3], ad);
            }
            #pragma unroll
            for (int np = 0; np < 2; np++) {
                uint32_t bd = Bs + (uint32_t)((warp_n + np * 16) * ROWB + kk * 32) + boff;
                LDSM4(b[2 * np][0], b[2 * np][1], b[2 * np + 1][0], b[2 * np + 1][1], bd);
            }
            #pragma unroll
            for (int mt = 0; mt < 4; mt++)
                #pragma unroll
                for (int nt = 0; nt < 4; nt++)
                    asm volatile(
                        "mma.sync.aligned.m16n8k16.row.col.f32.f16.f16.f32 "
                        "{%0,%1,%2,%3},{%4,%5,%6,%7},{%8,%9},{%0,%1,%2,%3};"
                        : "+f"(acc[mt][nt][0]), "+f"(acc[mt][nt][1]),
                          "+f"(acc[mt][nt][2]), "+f"(acc[mt][nt][3])
                        : "r"(a[mt][0]), "r"(a[mt][1]), "r"(a[mt][2]), "r"(a[mt][3]),
                          "r"(b[nt][0]), "r"(b[nt][1]));
        }
        __syncthreads();
        if (c + 2 < NCH) loadc(c & 1, c + 2);
        asm volatile("cp.async.commit_group;" ::: "memory");
    }

    #pragma unroll
    for (int mt = 0; mt < 4; mt++) {
        int row0 = mBase + warp_m + mt * 16 + gid;
        #pragma unroll
        for (int nt = 0; nt < 4; nt++) {
            int col = nBase + warp_n + nt * 8 + 2 * tig;
            *(float2*)(g_logits + (size_t)row0 * NM + col) =
                make_float2(acc[mt][nt][0], acc[mt][nt][1]);
            *(float2*)(g_logits + (size_t)(row0 + 8) * NM + col) =
                make_float2(acc[mt][nt][2], acc[mt][nt][3]);
        }
    }
}

// ---------------------------------------------------------------------------
// Kernel 3: per-sample reductions; top-K via radix select (value multiset)
// ---------------------------------------------------------------------------
__device__ __forceinline__ float blockMaxF(float v, float* scratch) {
    int t = threadIdx.x;
    #pragma unroll
    for (int o = 16; o > 0; o >>= 1) v = fmaxf(v, __shfl_down_sync(0xffffffffu, v, o));
    if ((t & 31) == 0) scratch[t >> 5] = v;
    __syncthreads();
    if (t < 8) {
        float w = scratch[t];
        #pragma unroll
        for (int o = 4; o > 0; o >>= 1) w = fmaxf(w, __shfl_down_sync(0xffu, w, o));
        if (t == 0) scratch[0] = w;
    }
    __syncthreads();
    float r = scratch[0];
    __syncthreads();
    return r;
}
__device__ __forceinline__ float blockSumF(float v, float* scratch) {
    int t = threadIdx.x;
    #pragma unroll
    for (int o = 16; o > 0; o >>= 1) v += __shfl_down_sync(0xffffffffu, v, o);
    if ((t & 31) == 0) scratch[t >> 5] = v;
    __syncthreads();
    if (t < 8) {
        float w = scratch[t];
        #pragma unroll
        for (int o = 4; o > 0; o >>= 1) w += __shfl_down_sync(0xffu, w, o);
        if (t == 0) scratch[0] = w;
    }
    __syncthreads();
    float r = scratch[0];
    __syncthreads();
    return r;
}

__global__ void __launch_bounds__(256) krow(const int* __restrict__ labels,
                                            const int* __restrict__ cams) {
    extern __shared__ float sv[];                 // NM floats (64 KB)
    __shared__ int hist[256];
    __shared__ int ssc[256];
    __shared__ float fred[8];
    __shared__ float s_ori[CCAM];
    __shared__ float s_maxori;
    __shared__ uint32_t s_prefix;
    __shared__ int s_rem;

    int b = blockIdx.x;
    int t = threadIdx.x;
    const float* row = g_logits + (size_t)b * NM;
    for (int i = t; i < NM; i += 256) sv[i] = row[i];
    __syncthreads();

    int cam = cams[b];
    int lab = labels[b];

    // ---- intra-camera CE (unmasked values) ----
    int base = cam * P_;
    float mx = -INFINITY;
    for (int i = t; i < P_; i += 256) mx = fmaxf(mx, sv[base + i]);
    float mxall = blockMaxF(mx, fred);
    float s = 0.f;
    for (int i = t; i < P_; i += 256) s += expf((sv[base + i] - mxall) * TINV);
    float sall = blockSumF(s, fred);
    if (t == 0) {
        float lse = mxall * TINV + logf(sall);
        g_ce[b] = lse - sv[base + lab] * TINV;
    }
    __syncthreads();

    // ---- inter-camera: capture positives, mask them ----
    if (t == 0) {
        float mo = -INFINITY;
        #pragma unroll
        for (int c = 0; c < CCAM; c++) {
            s_ori[c] = sv[lab + P_ * c];
            mo = fmaxf(mo, s_ori[c]);
        }
        #pragma unroll
        for (int c = 0; c < CCAM; c++) sv[lab + P_ * c] = -10000.0f;
        s_maxori = mo;
    }
    __syncthreads();

    // ---- global max of masked values ----
    float gm = -INFINITY;
    #pragma unroll 8
    for (int j = 0; j < NM / 256; j++) gm = fmaxf(gm, sv[t + 256 * j]);
    float gmax = blockMaxF(gm, fred);
    float m = fmaxf(gmax, s_maxori);

    // ---- radix select: exact rank-KTOP threshold over ordered uints ----
    uint32_t prefix = 0u, pmask = 0u;
    int rem = KTOP;
    #pragma unroll 1
    for (int pass = 0; pass < 4; pass++) {
        int shift = 24 - 8 * pass;
        hist[t] = 0;
        __syncthreads();
        #pragma unroll 8
        for (int j = 0; j < NM / 256; j++) {
            uint32_t u = ordu(sv[t + 256 * j]);
            if ((u & pmask) == prefix)
                atomicAdd(&hist[(u >> shift) & 0xFF], 1);
        }
        __syncthreads();
        ssc[t] = hist[t];
        __syncthreads();
        // inclusive suffix scan: ssc[t] = sum_{j>=t} hist[j]
        #pragma unroll
        for (int o = 1; o < 256; o <<= 1) {
            int v = ssc[t] + ((t + o < 256) ? ssc[t + o] : 0);
            __syncthreads();
            ssc[t] = v;
            __syncthreads();
        }
        int Sincl = ssc[t];
        int Sexcl = Sincl - hist[t];
        if (Sexcl < rem && rem <= Sincl) {
            s_prefix = prefix | ((uint32_t)t << shift);
            s_rem = rem - Sexcl;
        }
        __syncthreads();
        prefix = s_prefix;
        rem = s_rem;
        pmask |= (0xFFu << shift);
        __syncthreads();
    }
    uint32_t thr = prefix;
    float tf = (thr & 0x80000000u) ? __uint_as_float(thr ^ 0x80000000u)
                                   : __uint_as_float(~thr);

    // ---- sum exp over values strictly above threshold ----
    float ssum = 0.f;
    #pragma unroll 8
    for (int j = 0; j < NM / 256; j++) {
        float v = sv[t + 256 * j];
        if (ordu(v) > thr) ssum += expf((v - m) * TINV);
    }
    float tot = blockSumF(ssum, fred);
    if (t == 0) {
        tot += (float)rem * expf((tf - m) * TINV);      // ties at threshold
        float mean = 0.f;
        #pragma unroll
        for (int c = 0; c < CCAM; c++) {
            tot += expf((s_ori[c] - m) * TINV);
            mean += s_ori[c];
        }
        float lse = m * TINV + logf(tot);
        g_lossk[b] = lse - mean * TINV / (float)CCAM;
    }
}

// ---------------------------------------------------------------------------
// Kernel 4: deterministic per-camera segment means -> 2 scalars
// ---------------------------------------------------------------------------
__global__ void __launch_bounds__(256) kfinal(const int* __restrict__ cams,
                                              float* __restrict__ out) {
    __shared__ int sc_cam[B_];
    __shared__ float sce[B_], slk[B_];
    __shared__ float mce[CCAM], mlk[CCAM];
    int t = threadIdx.x;
    sc_cam[t] = cams[t];
    sce[t] = g_ce[t];
    slk[t] = g_lossk[t];
    __syncthreads();
    if (t < CCAM) {
        float sc = 0.f, sl = 0.f; int cnt = 0;
        for (int i = 0; i < B_; i++) {
            if (sc_cam[i] == t) { sc += sce[i]; sl += slk[i]; cnt++; }
        }
        mce[t] = (cnt > 0) ? sc / (float)cnt : 0.f;
        mlk[t] = (cnt > 0) ? sl / (float)cnt : 0.f;
    }
    __syncthreads();
    if (t == 0) {
        float li = 0.f, lk = 0.f;
        #pragma unroll
        for (int c = 0; c < CCAM; c++) { li += mce[c]; lk += mlk[c]; }
        out[0] = li;
        out[1] = 0.5f * lk;   // LOSS_WEIGHT
    }
}

// ---------------------------------------------------------------------------
extern "C" void kernel_launch(void* const* d_in, const int* in_sizes, int n_in,
                              void* d_out, int out_size) {
    const float* x      = (const float*)d_in[0];
    const int*   labels = (const int*)d_in[1];
    const int*   cams   = (const int*)d_in[2];
    const float* tempV  = (const float*)d_in[3];
    float* out = (float*)d_out;

    kcvt<<<(NM * D_ / 8) / 256, 256>>>(tempV);
    knorm<<<B_, 256>>>(x);

    cudaFuncSetAttribute(kgemm, cudaFuncAttributeMaxDynamicSharedMemorySize,
                         GEMM_SMEM);
    dim3 g(NM / BN, B_ / BM);          // 128 x 2 = 256 CTAs
    kgemm<<<g, 256, GEMM_SMEM>>>();

    cudaFuncSetAttribute(krow, cudaFuncAttributeMaxDynamicSharedMemorySize,
                         NM * (int)sizeof(float) + 1024);
    krow<<<B_, 256, NM * sizeof(float)>>>(labels, cams);

    kfinal<<<1, 256>>>(cams, out);
}

// round 7
// speedup vs baseline: 1.5403x; 1.0727x over previous
#include <cuda_runtime.h>
#include <cuda_fp16.h>
#include <math.h>
#include <stdint.h>

#define B_    256
#define D_    2048
#define NM    16384      // C_CAM * P
#define P_    2048
#define CCAM  8
#define KTOP  50
#define TINV  (1.0f/0.07f)

// scratch (static device globals — no allocation allowed)
__device__ __align__(16) uint32_t g_xh[B_ * D_ / 2];   // fp16 normalized inputs, 1 MB
__device__ float g_logits[B_ * NM];                    // all_logits, 16 MB
__device__ float g_ce[B_];
__device__ float g_lossk[B_];
__device__ int   g_cnt = 0;                            // last-CTA counter

// ---------------------------------------------------------------------------
__device__ __forceinline__ uint32_t smem_u32(const void* p) {
    uint32_t a;
    asm("{ .reg .u64 t; cvta.to.shared.u64 t, %1; cvt.u32.u64 %0, t; }"
        : "=r"(a) : "l"(p));
    return a;
}
__device__ __forceinline__ void cpa16(uint32_t s, const void* g) {
    asm volatile("cp.async.cg.shared.global [%0], [%1], 16;" :: "r"(s), "l"(g) : "memory");
}
// pack two fp32 -> f16x2 (memory order: first arg low)
__device__ __forceinline__ uint32_t packh(float2 v) {
    uint32_t r;
    asm("cvt.rn.f16x2.f32 %0, %1, %2;" : "=r"(r) : "f"(v.y), "f"(v.x));
    return r;
}
__device__ __forceinline__ uint32_t ordu(float f) {
    uint32_t u = __float_as_uint(f);
    return (u & 0x80000000u) ? ~u : (u | 0x80000000u);
}
#define LDSM4(r0, r1, r2, r3, a) \
    asm volatile("ldmatrix.sync.aligned.m8n8.x4.shared.b16 {%0,%1,%2,%3}, [%4];" \
                 : "=r"(r0), "=r"(r1), "=r"(r2), "=r"(r3) : "r"(a))

// ---------------------------------------------------------------------------
// Kernel 1: L2-normalize each input row -> fp16
// ---------------------------------------------------------------------------
__global__ void __launch_bounds__(256) knorm(const float* __restrict__ x) {
    __shared__ float red[8];
    int b = blockIdx.x;
    int t = threadIdx.x;
    const float* row = x + (size_t)b * D_;
    float s = 0.f;
    for (int i = t; i < D_; i += 256) { float v = row[i]; s += v * v; }
    #pragma unroll
    for (int o = 16; o > 0; o >>= 1) s += __shfl_down_sync(0xffffffffu, s, o);
    if ((t & 31) == 0) red[t >> 5] = s;
    __syncthreads();
    if (t < 8) {
        float w = red[t];
        #pragma unroll
        for (int o = 4; o > 0; o >>= 1) w += __shfl_down_sync(0xffu, w, o);
        if (t == 0) red[0] = w;
    }
    __syncthreads();
    float inv = rsqrtf(red[0]);
    const float2* r2 = (const float2*)row;
    for (int i = t; i < D_ / 2; i += 256) {
        float2 v = r2[i];
        g_xh[b * (D_ / 2) + i] = packh(make_float2(v.x * inv, v.y * inv));
    }
}

// ---------------------------------------------------------------------------
// Kernel 2: fp16 GEMM  C[256,16384] = xh @ tempV^T, B converted on the fly
// CTA tile 256x64 (full M per CTA -> tempV read exactly once, no kcvt).
// A: cp.async fp16 double buffer.  B: LDG fp32 -> cvt -> STS, reg-staged.
// ---------------------------------------------------------------------------
#define BMT 256
#define BNT 64
#define BKH 64                    // halfs per K chunk
#define NCH (D_ / BKH)            // 32
#define ROWB 144                  // bytes per SMEM row (128 data + 16 pad)
#define ASTG (BMT * ROWB)         // 36864 B per A stage
#define BSTG (BNT * ROWB)         // 9216 B per B stage
#define GEMM_SMEM (2 * ASTG + 2 * BSTG)   // 92160 B

__global__ void __launch_bounds__(256, 2) kgemm(const float* __restrict__ Bmat) {
    extern __shared__ char sm[];
    uint32_t sbase = smem_u32(sm);
    int t = threadIdx.x, lane = t & 31, wid = t >> 5;
    int warp_m = (wid & 3) * 64, warp_n = (wid >> 2) * 32;
    int gid = lane >> 2, tig = lane & 3;
    int nBase = blockIdx.x * BNT;

    float acc[4][4][4];
    #pragma unroll
    for (int i = 0; i < 4; i++)
        #pragma unroll
        for (int j = 0; j < 4; j++)
            #pragma unroll
            for (int q = 0; q < 4; q++) acc[i][j][q] = 0.f;

    const char* xhb = (const char*)g_xh;
    int brow = t >> 2;                     // 0..63 : B row this thread loads

    auto loada = [&](int stage, int c) {
        int k0 = c * BKH;
        uint32_t As = sbase + stage * ASTG;
        #pragma unroll
        for (int r = 0; r < 8; r++) {
            int i = t + r * 256, row = i >> 3, q = i & 7;
            cpa16(As + (uint32_t)(row * ROWB + q * 16),
                  xhb + ((size_t)row * D_ + k0 + q * 8) * 2);
        }
    };
    auto ldgb = [&](float4* rb, int c) {
        int k0 = c * BKH;
        const float* src = Bmat + (size_t)(nBase + brow) * D_ + k0;
        #pragma unroll
        for (int r = 0; r < 4; r++)
            rb[r] = *(const float4*)(src + ((t & 3) + 4 * r) * 4);
    };
    auto stsb = [&](int stage, const float4* rb) {
        uint32_t Bs = sbase + 2 * ASTG + stage * BSTG + (uint32_t)(brow * ROWB);
        #pragma unroll
        for (int r = 0; r < 4; r++) {
            int c4 = (t & 3) + 4 * r;
            uint32_t lo = packh(make_float2(rb[r].x, rb[r].y));
            uint32_t hi = packh(make_float2(rb[r].z, rb[r].w));
            asm volatile("st.shared.v2.b32 [%0], {%1,%2};"
                         :: "r"(Bs + (uint32_t)(8 * c4)), "r"(lo), "r"(hi) : "memory");
        }
    };

    uint32_t aoff = (uint32_t)((lane & 15) * ROWB + (lane >> 4) * 16);
    uint32_t boff = (uint32_t)(((lane & 7) + ((lane >> 4) << 3)) * ROWB
                               + (((lane >> 3) & 1) * 16));

    float4 rb[4];
    ldgb(rb, 0);
    loada(0, 0); asm volatile("cp.async.commit_group;" ::: "memory");
    loada(1, 1); asm volatile("cp.async.commit_group;" ::: "memory");

    for (int c = 0; c < NCH; c++) {
        int s = c & 1;
        stsb(s, rb);
        asm volatile("cp.async.wait_group 1;" ::: "memory");
        __syncthreads();
        if (c + 1 < NCH) ldgb(rb, c + 1);

        uint32_t As = sbase + s * ASTG;
        uint32_t Bs = sbase + 2 * ASTG + s * BSTG;
        #pragma unroll
        for (int kk = 0; kk < 4; kk++) {
            uint32_t a[4][4], b[4][2];
            #pragma unroll
            for (int mt = 0; mt < 4; mt++) {
                uint32_t ad = As + (uint32_t)((warp_m + mt * 16) * ROWB + kk * 32) + aoff;
                LDSM4(a[mt][0], a[mt][1], a[mt][2], a[mt][3], ad);
            }
            #pragma unroll
            for (int np = 0; np < 2; np++) {
                uint32_t bd = Bs + (uint32_t)((warp_n + np * 16) * ROWB + kk * 32) + boff;
                LDSM4(b[2 * np][0], b[2 * np][1], b[2 * np + 1][0], b[2 * np + 1][1], bd);
            }
            #pragma unroll
            for (int mt = 0; mt < 4; mt++)
                #pragma unroll
                for (int nt = 0; nt < 4; nt++)
                    asm volatile(
                        "mma.sync.aligned.m16n8k16.row.col.f32.f16.f16.f32 "
                        "{%0,%1,%2,%3},{%4,%5,%6,%7},{%8,%9},{%0,%1,%2,%3};"
                        : "+f"(acc[mt][nt][0]), "+f"(acc[mt][nt][1]),
                          "+f"(acc[mt][nt][2]), "+f"(acc[mt][nt][3])
                        : "r"(a[mt][0]), "r"(a[mt][1]), "r"(a[mt][2]), "r"(a[mt][3]),
                          "r"(b[nt][0]), "r"(b[nt][1]));
        }
        __syncthreads();
        if (c + 2 < NCH) loada(s, c + 2);
        asm volatile("cp.async.commit_group;" ::: "memory");
    }

    #pragma unroll
    for (int mt = 0; mt < 4; mt++) {
        int row0 = warp_m + mt * 16 + gid;
        #pragma unroll
        for (int nt = 0; nt < 4; nt++) {
            int col = nBase + warp_n + nt * 8 + 2 * tig;
            *(float2*)(g_logits + (size_t)row0 * NM + col) =
                make_float2(acc[mt][nt][0], acc[mt][nt][1]);
            *(float2*)(g_logits + (size_t)(row0 + 8) * NM + col) =
                make_float2(acc[mt][nt][2], acc[mt][nt][3]);
        }
    }
}

// ---------------------------------------------------------------------------
// Kernel 3: per-sample reductions (radix top-K, m=1 shift) + fused finalize
// ---------------------------------------------------------------------------
__device__ __forceinline__ float blockSumF(float v, float* scratch) {
    int t = threadIdx.x;
    #pragma unroll
    for (int o = 16; o > 0; o >>= 1) v += __shfl_down_sync(0xffffffffu, v, o);
    if ((t & 31) == 0) scratch[t >> 5] = v;
    __syncthreads();
    if (t < 8) {
        float w = scratch[t];
        #pragma unroll
        for (int o = 4; o > 0; o >>= 1) w += __shfl_down_sync(0xffu, w, o);
        if (t == 0) scratch[0] = w;
    }
    __syncthreads();
    float r = scratch[0];
    __syncthreads();
    return r;
}

__global__ void __launch_bounds__(256) krow(const int* __restrict__ labels,
                                            const int* __restrict__ cams,
                                            float* __restrict__ out) {
    extern __shared__ float sv[];                 // NM floats (64 KB)
    __shared__ int hist[256];
    __shared__ float fred[8];
    __shared__ float s_ori[CCAM];
    __shared__ uint32_t s_prefix;
    __shared__ int s_rem;
    __shared__ int s_last;
    __shared__ int sc_cam[B_];
    __shared__ float sce[B_], slk[B_];

    int b = blockIdx.x;
    int t = threadIdx.x;
    const float4* row4 = (const float4*)(g_logits + (size_t)b * NM);
    #pragma unroll
    for (int j = 0; j < 16; j++)
        ((float4*)sv)[t + 256 * j] = row4[t + 256 * j];
    __syncthreads();

    int cam = cams[b];
    int lab = labels[b];

    // ---- intra-camera CE with fixed shift m=1 (|cosine| <= 1) ----
    int base = cam * P_;
    float s = 0.f;
    #pragma unroll 4
    for (int i = t; i < P_; i += 256) s += expf((sv[base + i] - 1.0f) * TINV);
    float sall = blockSumF(s, fred);
    if (t == 0) {
        float lse = TINV + logf(sall);
        g_ce[b] = lse - sv[base + lab] * TINV;
    }
    __syncthreads();

    // ---- inter-camera: capture positives, mask them ----
    if (t == 0) {
        #pragma unroll
        for (int c = 0; c < CCAM; c++) s_ori[c] = sv[lab + P_ * c];
        #pragma unroll
        for (int c = 0; c < CCAM; c++) sv[lab + P_ * c] = -10000.0f;
    }
    __syncthreads();

    // ---- radix select: exact rank-KTOP threshold over ordered uints ----
    uint32_t prefix = 0u, pmask = 0u;
    int rem = KTOP;
    #pragma unroll 1
    for (int pass = 0; pass < 4; pass++) {
        int shift = 24 - 8 * pass;
        hist[t] = 0;
        __syncthreads();
        #pragma unroll 8
        for (int j = 0; j < NM / 256; j++) {
            uint32_t u = ordu(sv[t + 256 * j]);
            if ((u & pmask) == prefix)
                atomicAdd(&hist[(u >> shift) & 0xFF], 1);
        }
        __syncthreads();
        if (t < 32) {                       // warp-0 suffix scan over 256 bins
            int h[8];
            #pragma unroll
            for (int j = 0; j < 8; j++) h[j] = hist[t * 8 + j];
            int tot = 0;
            #pragma unroll
            for (int j = 0; j < 8; j++) tot += h[j];
            int suf = tot;
            #pragma unroll
            for (int o = 1; o < 32; o <<= 1) {
                int q = __shfl_down_sync(0xffffffffu, suf, o);
                if (t + o < 32) suf += q;
            }
            int cum = suf - tot;            // count strictly above this lane's bins
            #pragma unroll
            for (int j = 7; j >= 0; j--) {
                int incl = cum + h[j];
                if (cum < rem && rem <= incl) {
                    s_prefix = prefix | ((uint32_t)(t * 8 + j) << shift);
                    s_rem = rem - cum;
                }
                cum = incl;
            }
        }
        __syncthreads();
        prefix = s_prefix;
        rem = s_rem;
        pmask |= (0xFFu << shift);
    }
    uint32_t thr = prefix;
    float tf = (thr & 0x80000000u) ? __uint_as_float(thr ^ 0x80000000u)
                                   : __uint_as_float(~thr);

    // ---- sum exp over values strictly above threshold (m = 1) ----
    float ssum = 0.f;
    #pragma unroll 8
    for (int j = 0; j < NM / 256; j++) {
        float v = sv[t + 256 * j];
        if (ordu(v) > thr) ssum += expf((v - 1.0f) * TINV);
    }
    float tot = blockSumF(ssum, fred);
    if (t == 0) {
        tot += (float)rem * expf((tf - 1.0f) * TINV);    // ties at threshold
        float mean = 0.f;
        #pragma unroll
        for (int c = 0; c < CCAM; c++) {
            tot += expf((s_ori[c] - 1.0f) * TINV);
            mean += s_ori[c];
        }
        float lse = TINV + logf(tot);
        g_lossk[b] = lse - mean * TINV / (float)CCAM;
    }

    // ---- fused finalize: last CTA computes segment means ----
    if (t == 0) {
        __threadfence();
        int prev = atomicAdd(&g_cnt, 1);
        s_last = (prev == B_ - 1) ? 1 : 0;
    }
    __syncthreads();
    if (!s_last) return;
    if (t == 0) g_cnt = 0;                  // reset for next replay
    volatile float* vce = g_ce;
    volatile float* vlk = g_lossk;
    sc_cam[t] = cams[t];
    sce[t] = vce[t];
    slk[t] = vlk[t];
    __syncthreads();
    __shared__ float mce[CCAM], mlk[CCAM];
    if (t < CCAM) {
        float sc = 0.f, sl = 0.f; int cnt = 0;
        for (int i = 0; i < B_; i++) {
            if (sc_cam[i] == t) { sc += sce[i]; sl += slk[i]; cnt++; }
        }
        mce[t] = (cnt > 0) ? sc / (float)cnt : 0.f;
        mlk[t] = (cnt > 0) ? sl / (float)cnt : 0.f;
    }
    __syncthreads();
    if (t == 0) {
        float li = 0.f, lk = 0.f;
        #pragma unroll
        for (int c = 0; c < CCAM; c++) { li += mce[c]; lk += mlk[c]; }
        out[0] = li;
        out[1] = 0.5f * lk;                 // LOSS_WEIGHT
    }
}

// ---------------------------------------------------------------------------
extern "C" void kernel_launch(void* const* d_in, const int* in_sizes, int n_in,
                              void* d_out, int out_size) {
    const float* x      = (const float*)d_in[0];
    const int*   labels = (const int*)d_in[1];
    const int*   cams   = (const int*)d_in[2];
    const float* tempV  = (const float*)d_in[3];
    float* out = (float*)d_out;

    knorm<<<B_, 256>>>(x);

    cudaFuncSetAttribute(kgemm, cudaFuncAttributeMaxDynamicSharedMemorySize,
                         GEMM_SMEM);
    kgemm<<<NM / BNT, 256, GEMM_SMEM>>>(tempV);    // 256 CTAs

    cudaFuncSetAttribute(krow, cudaFuncAttributeMaxDynamicSharedMemorySize,
                         NM * (int)sizeof(float) + 1024);
    krow<<<B_, 256, NM * sizeof(float)>>>(labels, cams, out);
}

// round 8
// speedup vs baseline: 1.6931x; 1.0992x over previous
#include <cuda_runtime.h>
#include <cuda_fp16.h>
#include <math.h>
#include <stdint.h>

#define B_    256
#define D_    2048
#define NM    16384      // C_CAM * P
#define P_    2048
#define CCAM  8
#define KTOP  50
#define TINV  (1.0f/0.07f)

// scratch (static device globals — no allocation allowed)
__device__ __align__(16) uint32_t g_xh[B_ * D_ / 2];   // fp16 normalized inputs, 1 MB
__device__ float g_logits[B_ * NM];                    // all_logits, 16 MB
__device__ float g_ce[B_];
__device__ float g_lossk[B_];
__device__ int   g_cnt = 0;                            // last-CTA counter

// ---------------------------------------------------------------------------
__device__ __forceinline__ uint32_t smem_u32(const void* p) {
    uint32_t a;
    asm("{ .reg .u64 t; cvta.to.shared.u64 t, %1; cvt.u32.u64 %0, t; }"
        : "=r"(a) : "l"(p));
    return a;
}
__device__ __forceinline__ void cpa16(uint32_t s, const void* g) {
    asm volatile("cp.async.cg.shared.global [%0], [%1], 16;" :: "r"(s), "l"(g) : "memory");
}
__device__ __forceinline__ uint32_t packh(float lo, float hi) {
    uint32_t r;
    asm("cvt.rn.f16x2.f32 %0, %1, %2;" : "=r"(r) : "f"(hi), "f"(lo));
    return r;
}
__device__ __forceinline__ uint32_t ordu(float f) {
    uint32_t u = __float_as_uint(f);
    return (u & 0x80000000u) ? ~u : (u | 0x80000000u);
}
#define LDSM4(r0, r1, r2, r3, a) \
    asm volatile("ldmatrix.sync.aligned.m8n8.x4.shared.b16 {%0,%1,%2,%3}, [%4];" \
                 : "=r"(r0), "=r"(r1), "=r"(r2), "=r"(r3) : "r"(a))

// ---------------------------------------------------------------------------
// Kernel 1: L2-normalize each input row -> fp16 (single pass, register row)
// ---------------------------------------------------------------------------
__global__ void __launch_bounds__(256) knorm(const float* __restrict__ x) {
    __shared__ float red[8];
    int b = blockIdx.x, t = threadIdx.x;
    const float4* row = (const float4*)(x + (size_t)b * D_);
    float4 v0 = row[2 * t], v1 = row[2 * t + 1];
    float s = v0.x * v0.x + v0.y * v0.y + v0.z * v0.z + v0.w * v0.w
            + v1.x * v1.x + v1.y * v1.y + v1.z * v1.z + v1.w * v1.w;
    #pragma unroll
    for (int o = 16; o > 0; o >>= 1) s += __shfl_down_sync(0xffffffffu, s, o);
    if ((t & 31) == 0) red[t >> 5] = s;
    __syncthreads();
    if (t < 8) {
        float w = red[t];
        #pragma unroll
        for (int o = 4; o > 0; o >>= 1) w += __shfl_down_sync(0xffu, w, o);
        if (t == 0) red[0] = w;
    }
    __syncthreads();
    float inv = rsqrtf(red[0]);
    uint4 o;
    o.x = packh(v0.x * inv, v0.y * inv);
    o.y = packh(v0.z * inv, v0.w * inv);
    o.z = packh(v1.x * inv, v1.y * inv);
    o.w = packh(v1.z * inv, v1.w * inv);
    ((uint4*)g_xh)[b * (D_ / 8) + t] = o;
}

// ---------------------------------------------------------------------------
// Kernel 2: fp16 GEMM  C[256,16384] = xh @ tempV^T
// CTA tile 256x64 (full M -> tempV read exactly once). BKH=32 halfs/chunk.
// A: cp.async fp16 double buffer.  B: cp.async fp32 -> smem cvt -> fp16 smem.
// ---------------------------------------------------------------------------
#define BMT 256
#define BNT 64
#define BKH 32
#define NCHG (D_ / BKH)          // 64
#define ROWA 80                  // 64 B data + 16 pad (LDSM conflict-free)
#define ASTG (BMT * ROWA)        // 20480 B
#define BSTG (BNT * ROWA)        // 5120 B
#define B32S (BNT * BKH * 4)     // 8192 B fp32 staging
#define GEMM_SMEM (2 * ASTG + 2 * BSTG + 2 * B32S)   // 67584 B

__global__ void __launch_bounds__(256, 2) kgemm(const float* __restrict__ Bmat) {
    extern __shared__ char sm[];
    uint32_t sbase = smem_u32(sm);
    int t = threadIdx.x, lane = t & 31, wid = t >> 5;
    int warp_m = (wid & 3) * 64, warp_n = (wid >> 2) * 32;
    int gid = lane >> 2, tig = lane & 3;
    int nBase = blockIdx.x * BNT;

    float acc[4][4][4];
    #pragma unroll
    for (int i = 0; i < 4; i++)
        #pragma unroll
        for (int j = 0; j < 4; j++)
            #pragma unroll
            for (int q = 0; q < 4; q++) acc[i][j][q] = 0.f;

    const char* xhb = (const char*)g_xh;

    auto loadAB = [&](int stage, int c) {
        int k0 = c * BKH;
        uint32_t As = sbase + stage * ASTG;
        // A: 256 rows x 64 B -> 4 cp.async per thread
        #pragma unroll
        for (int r = 0; r < 4; r++) {
            int i = t + r * 256, row = i >> 2, q = i & 3;
            cpa16(As + (uint32_t)(row * ROWA + q * 16),
                  xhb + ((size_t)row * D_ + k0 + q * 8) * 2);
        }
        // B fp32: 64 rows x 128 B -> 2 cp.async per thread
        uint32_t B3 = sbase + 2 * ASTG + 2 * BSTG + stage * B32S;
        #pragma unroll
        for (int r = 0; r < 2; r++) {
            int i = t + r * 256, row = i >> 3, q = i & 7;
            cpa16(B3 + (uint32_t)(row * 128 + q * 16),
                  Bmat + (size_t)(nBase + row) * D_ + k0 + q * 4);
        }
    };

    auto cvtB = [&](int stage) {
        uint32_t B3 = sbase + 2 * ASTG + 2 * BSTG + stage * B32S + (uint32_t)(t * 32);
        uint32_t B6 = sbase + 2 * ASTG + stage * BSTG;
        float4 u, v;
        asm volatile("ld.shared.v4.f32 {%0,%1,%2,%3}, [%4];"
                     : "=f"(u.x), "=f"(u.y), "=f"(u.z), "=f"(u.w) : "r"(B3));
        asm volatile("ld.shared.v4.f32 {%0,%1,%2,%3}, [%4];"
                     : "=f"(v.x), "=f"(v.y), "=f"(v.z), "=f"(v.w) : "r"(B3 + 16));
        uint32_t p0 = packh(u.x, u.y), p1 = packh(u.z, u.w);
        uint32_t p2 = packh(v.x, v.y), p3 = packh(v.z, v.w);
        int e = t * 8, row = e >> 5, col = e & 31;
        asm volatile("st.shared.v4.b32 [%0], {%1,%2,%3,%4};"
                     :: "r"(B6 + (uint32_t)(row * ROWA + col * 2)),
                        "r"(p0), "r"(p1), "r"(p2), "r"(p3) : "memory");
    };

    uint32_t aoff = (uint32_t)((lane & 15) * ROWA + (lane >> 4) * 16);
    uint32_t boff = (uint32_t)(((lane & 7) + ((lane >> 4) << 3)) * ROWA
                               + (((lane >> 3) & 1) * 16));

    loadAB(0, 0); asm volatile("cp.async.commit_group;" ::: "memory");
    loadAB(1, 1); asm volatile("cp.async.commit_group;" ::: "memory");

    for (int c = 0; c < NCHG; c++) {
        int s = c & 1;
        asm volatile("cp.async.wait_group 1;" ::: "memory");
        __syncthreads();
        cvtB(s);
        __syncthreads();

        uint32_t As = sbase + s * ASTG;
        uint32_t Bs = sbase + 2 * ASTG + s * BSTG;
        #pragma unroll
        for (int kk = 0; kk < 2; kk++) {
            uint32_t a[4][4], b[4][2];
            #pragma unroll
            for (int mt = 0; mt < 4; mt++) {
                uint32_t ad = As + (uint32_t)((warp_m + mt * 16) * ROWA + kk * 32) + aoff;
                LDSM4(a[mt][0], a[mt][1], a[mt][2], a[mt][3], ad);
            }
            #pragma unroll
            for (int np = 0; np < 2; np++) {
                uint32_t bd = Bs + (uint32_t)((warp_n + np * 16) * ROWA + kk * 32) + boff;
                LDSM4(b[2 * np][0], b[2 * np][1], b[2 * np + 1][0], b[2 * np + 1][1], bd);
            }
            #pragma unroll
            for (int mt = 0; mt < 4; mt++)
                #pragma unroll
                for (int nt = 0; nt < 4; nt++)
                    asm volatile(
                        "mma.sync.aligned.m16n8k16.row.col.f32.f16.f16.f32 "
                        "{%0,%1,%2,%3},{%4,%5,%6,%7},{%8,%9},{%0,%1,%2,%3};"
                        : "+f"(acc[mt][nt][0]), "+f"(acc[mt][nt][1]),
                          "+f"(acc[mt][nt][2]), "+f"(acc[mt][nt][3])
                        : "r"(a[mt][0]), "r"(a[mt][1]), "r"(a[mt][2]), "r"(a[mt][3]),
                          "r"(b[nt][0]), "r"(b[nt][1]));
        }
        __syncthreads();
        if (c + 2 < NCHG) loadAB(s, c + 2);
        asm volatile("cp.async.commit_group;" ::: "memory");
    }

    #pragma unroll
    for (int mt = 0; mt < 4; mt++) {
        int row0 = warp_m + mt * 16 + gid;
        #pragma unroll
        for (int nt = 0; nt < 4; nt++) {
            int col = nBase + warp_n + nt * 8 + 2 * tig;
            *(float2*)(g_logits + (size_t)row0 * NM + col) =
                make_float2(acc[mt][nt][0], acc[mt][nt][1]);
            *(float2*)(g_logits + (size_t)(row0 + 8) * NM + col) =
                make_float2(acc[mt][nt][2], acc[mt][nt][3]);
        }
    }
}

// ---------------------------------------------------------------------------
// Kernel 3: per-sample reductions; 3-pass radix select + fused finalize
// ---------------------------------------------------------------------------
__device__ __forceinline__ float blockSumF(float v, float* scratch) {
    int t = threadIdx.x;
    #pragma unroll
    for (int o = 16; o > 0; o >>= 1) v += __shfl_down_sync(0xffffffffu, v, o);
    if ((t & 31) == 0) scratch[t >> 5] = v;
    __syncthreads();
    if (t < 8) {
        float w = scratch[t];
        #pragma unroll
        for (int o = 4; o > 0; o >>= 1) w += __shfl_down_sync(0xffu, w, o);
        if (t == 0) scratch[0] = w;
    }
    __syncthreads();
    float r = scratch[0];
    __syncthreads();
    return r;
}

__global__ void __launch_bounds__(256) krow(const int* __restrict__ labels,
                                            const int* __restrict__ cams,
                                            float* __restrict__ out) {
    extern __shared__ float sv[];                 // NM floats (64 KB)
    __shared__ int hist[2048];
    __shared__ float fred[8];
    __shared__ int wtot[8], wexcl[8];
    __shared__ float s_ori[CCAM];
    __shared__ uint32_t s_prefix;
    __shared__ int s_rem;
    __shared__ int s_last;
    __shared__ int sc_cam[B_];
    __shared__ float sce[B_], slk[B_];

    int b = blockIdx.x;
    int t = threadIdx.x;
    int lane = t & 31, wid = t >> 5;

    #pragma unroll
    for (int j = 0; j < 8; j++) hist[t + 256 * j] = 0;
    __syncthreads();

    // ---- load row + pass-0 histogram (bits 31:21) fused ----
    const float4* row4 = (const float4*)(g_logits + (size_t)b * NM);
    #pragma unroll
    for (int j = 0; j < 16; j++) {
        float4 w = row4[t + 256 * j];
        ((float4*)sv)[t + 256 * j] = w;
        atomicAdd(&hist[ordu(w.x) >> 21], 1);
        atomicAdd(&hist[ordu(w.y) >> 21], 1);
        atomicAdd(&hist[ordu(w.z) >> 21], 1);
        atomicAdd(&hist[ordu(w.w) >> 21], 1);
    }
    __syncthreads();

    int cam = cams[b];
    int lab = labels[b];

    // ---- intra-camera CE, fixed shift m=1 (|cosine| <= 1), unmasked ----
    int base = cam * P_;
    float s = 0.f;
    #pragma unroll 4
    for (int i = t; i < P_; i += 256) s += expf((sv[base + i] - 1.0f) * TINV);
    float sall = blockSumF(s, fred);
    if (t == 0) g_ce[b] = TINV + logf(sall) - sv[base + lab] * TINV;
    __syncthreads();

    // ---- capture positives, mask them, fix pass-0 histogram ----
    if (t == 0) {
        #pragma unroll
        for (int c = 0; c < CCAM; c++) {
            float v = sv[lab + P_ * c];
            s_ori[c] = v;
            hist[ordu(v) >> 21] -= 1;
            sv[lab + P_ * c] = -10000.0f;
        }
    }
    __syncthreads();

    // ---- hierarchical bin selection (NBPT bins/thread, given shift) ----
    uint32_t prefix = 0u;
    int rem = KTOP;

    auto selectBins = [&](int nbpt, int shift) {
        int h[8], tot = 0;
        for (int j = 0; j < nbpt; j++) { h[j] = hist[t * nbpt + j]; tot += h[j]; }
        int suf = tot;
        #pragma unroll
        for (int o = 1; o < 32; o <<= 1) {
            int q = __shfl_down_sync(0xffffffffu, suf, o);
            if (lane + o < 32) suf += q;
        }
        if (lane == 0) wtot[wid] = suf;
        __syncthreads();
        if (t < 8) {
            int w = wtot[t], ws = w;
            #pragma unroll
            for (int o = 1; o < 8; o <<= 1) {
                int q = __shfl_down_sync(0xffu, ws, o);
                if (t + o < 8) ws += q;
            }
            wexcl[t] = ws - w;
        }
        __syncthreads();
        int above = wexcl[wid] + (suf - tot);
        for (int j = nbpt - 1; j >= 0; j--) {
            int incl = above + h[j];
            if (above < rem && rem <= incl) {
                s_prefix = prefix | ((uint32_t)(t * nbpt + j) << shift);
                s_rem = rem - above;
            }
            above = incl;
        }
        __syncthreads();
        prefix = s_prefix;
        rem = s_rem;
    };

    // pass 0: bits 31:21 (2048 bins) — histogram already built
    selectBins(8, 21);

    // pass 1: bits 20:10 (2048 bins) among prefix-matching values
    __syncthreads();
    #pragma unroll
    for (int j = 0; j < 8; j++) hist[t + 256 * j] = 0;
    __syncthreads();
    #pragma unroll 8
    for (int j = 0; j < NM / 256; j++) {
        uint32_t u = ordu(sv[t + 256 * j]);
        if ((u & 0xFFE00000u) == prefix)
            atomicAdd(&hist[(u >> 10) & 0x7FF], 1);
    }
    __syncthreads();
    selectBins(8, 10);

    // pass 2: bits 9:0 (1024 bins)
    __syncthreads();
    #pragma unroll
    for (int j = 0; j < 4; j++) hist[t + 256 * j] = 0;
    __syncthreads();
    #pragma unroll 8
    for (int j = 0; j < NM / 256; j++) {
        uint32_t u = ordu(sv[t + 256 * j]);
        if ((u & 0xFFFFFC00u) == prefix)
            atomicAdd(&hist[u & 0x3FF], 1);
    }
    __syncthreads();
    selectBins(4, 0);

    uint32_t thr = prefix;
    float tf = (thr & 0x80000000u) ? __uint_as_float(thr ^ 0x80000000u)
                                   : __uint_as_float(~thr);

    // ---- sum exp over values strictly above threshold (m = 1) ----
    float ssum = 0.f;
    #pragma unroll 8
    for (int j = 0; j < NM / 256; j++) {
        float v = sv[t + 256 * j];
        if (ordu(v) > thr) ssum += expf((v - 1.0f) * TINV);
    }
    float tot = blockSumF(ssum, fred);
    if (t == 0) {
        tot += (float)rem * expf((tf - 1.0f) * TINV);    // ties at threshold
        float mean = 0.f;
        #pragma unroll
        for (int c = 0; c < CCAM; c++) {
            tot += expf((s_ori[c] - 1.0f) * TINV);
            mean += s_ori[c];
        }
        g_lossk[b] = TINV + logf(tot) - mean * TINV / (float)CCAM;
    }

    // ---- fused finalize: last CTA computes segment means ----
    if (t == 0) {
        __threadfence();
        int prev = atomicAdd(&g_cnt, 1);
        s_last = (prev == B_ - 1) ? 1 : 0;
    }
    __syncthreads();
    if (!s_last) return;
    if (t == 0) g_cnt = 0;
    volatile float* vce = g_ce;
    volatile float* vlk = g_lossk;
    sc_cam[t] = cams[t];
    sce[t] = vce[t];
    slk[t] = vlk[t];
    __syncthreads();
    __shared__ float mce[CCAM], mlk[CCAM];
    if (t < CCAM) {
        float sc = 0.f, sl = 0.f; int cnt = 0;
        for (int i = 0; i < B_; i++) {
            if (sc_cam[i] == t) { sc += sce[i]; sl += slk[i]; cnt++; }
        }
        mce[t] = (cnt > 0) ? sc / (float)cnt : 0.f;
        mlk[t] = (cnt > 0) ? sl / (float)cnt : 0.f;
    }
    __syncthreads();
    if (t == 0) {
        float li = 0.f, lk = 0.f;
        #pragma unroll
        for (int c = 0; c < CCAM; c++) { li += mce[c]; lk += mlk[c]; }
        out[0] = li;
        out[1] = 0.5f * lk;                 // LOSS_WEIGHT
    }
}

// ---------------------------------------------------------------------------
extern "C" void kernel_launch(void* const* d_in, const int* in_sizes, int n_in,
                              void* d_out, int out_size) {
    const float* x      = (const float*)d_in[0];
    const int*   labels = (const int*)d_in[1];
    const int*   cams   = (const int*)d_in[2];
    const float* tempV  = (const float*)d_in[3];
    float* out = (float*)d_out;

    knorm<<<B_, 256>>>(x);

    cudaFuncSetAttribute(kgemm, cudaFuncAttributeMaxDynamicSharedMemorySize,
                         GEMM_SMEM);
    kgemm<<<NM / BNT, 256, GEMM_SMEM>>>(tempV);    // 256 CTAs

    cudaFuncSetAttribute(krow, cudaFuncAttributeMaxDynamicSharedMemorySize,
                         NM * (int)sizeof(float) + 1024);
    krow<<<B_, 256, NM * sizeof(float)>>>(labels, cams, out);
}